// round 3
// baseline (speedup 1.0000x reference)
#include <cuda_runtime.h>
#include <cstdint>

// CoordsToNRF: out[b, p] = atoms_flat[p] * (AU2KCALMOLA / MAX_NRF) / ||c_i - c_j||^2
// p = i*(i-1)/2 + j over the strict lower triangle of 128 atoms.
// B = 2048, NC2 = 8128.
//
// Round-3 structure: warp owns a 32-wide j-tile; cj held in registers,
// ci read as a single broadcast LDS.128 per row; rows swept i = j0+1..127.
// Triangle balanced by pairing tile w with tile 3-w across two batches.

#define N_ATOMS 128
#define NC2     8128
#define BLOCK_THREADS 128      // 4 warps
#define BATCHES_PER_BLOCK 2

__device__ __forceinline__ float nrf_scale() {
    return (float)(627.5095 * 0.529177 / 100.0);
}

__global__ __launch_bounds__(BLOCK_THREADS)
void coords_to_nrf_kernel(const float* __restrict__ coords,
                          const float* __restrict__ atoms_flat,
                          float* __restrict__ out) {
    // Coords for 2 batches, float4-padded: 2*128*16B = 4KB.
    __shared__ float4 sc[BATCHES_PER_BLOCK][N_ATOMS];

    const int warp = threadIdx.x >> 5;   // 0..3 -> j-tile
    const int lane = threadIdx.x & 31;
    const int bg   = blockIdx.x;         // batch pair index

    // ---- Stage coords for both batches (gmem [b][atom][3] -> smem float4) ----
    const float* cb = coords + (size_t)bg * BATCHES_PER_BLOCK * (N_ATOMS * 3);
    float* scf = reinterpret_cast<float*>(sc);
    #pragma unroll
    for (int idx = threadIdx.x; idx < BATCHES_PER_BLOCK * N_ATOMS * 3;
         idx += BLOCK_THREADS) {
        const int ba  = idx / 3;
        const int dim = idx - ba * 3;
        scf[ba * 4 + dim] = cb[idx];
    }
    __syncthreads();

    const float scale = nrf_scale();

    // Two assignments per warp: (tile=warp, batch 0) then (tile=3-warp, batch 1).
    // Rows per warp: (127-32w) + (31+32w) = 158 for every w -> balanced.
    #pragma unroll
    for (int a = 0; a < BATCHES_PER_BLOCK; a++) {
        const int jt = (a == 0) ? warp : (3 - warp);
        const int j0 = jt * 32;
        const int j  = j0 + lane;

        const float4 cj = sc[a][j];                 // registers for the sweep
        float* ob = out + ((size_t)bg * BATCHES_PER_BLOCK + a) * NC2;

        int pbase = ((j0 + 1) * j0) >> 1;           // p at row i = j0+1, col 0

        #pragma unroll 4
        for (int i = j0 + 1; i < N_ATOMS; i++) {
            const float4 ci = sc[a][i];             // uniform addr -> broadcast
            const float dx = ci.x - cj.x;
            const float dy = ci.y - cj.y;
            const float dz = ci.z - cj.z;
            const float d2 = fmaf(dx, dx, fmaf(dy, dy, dz * dz));

            if (j < i) {                            // partial rows in diag tile
                const int p = pbase + j;
                const float aval = __ldg(&atoms_flat[p]) * scale;
                ob[p] = __fdividef(aval, d2);       // MUFU.RCP + FMUL
            }
            pbase += i;
        }
    }
}

extern "C" void kernel_launch(void* const* d_in, const int* in_sizes, int n_in,
                              void* d_out, int out_size) {
    const float* coords     = (const float*)d_in[0];  // [2048, 128, 3] f32
    const float* atoms_flat = (const float*)d_in[1];  // [8128] f32
    float* out = (float*)d_out;                       // [2048, 8128] f32

    const int batch = in_sizes[0] / (N_ATOMS * 3);    // 2048
    coords_to_nrf_kernel<<<batch / BATCHES_PER_BLOCK, BLOCK_THREADS>>>(
        coords, atoms_flat, out);
}

// round 4
// speedup vs baseline: 1.2686x; 1.2686x over previous
#include <cuda_runtime.h>
#include <cstdint>

// CoordsToNRF: out[b, p] = atoms_flat[p] * (AU2KCALMOLA / MAX_NRF) / ||c_i - c_j||^2
// p = i*(i-1)/2 + j over the strict lower triangle of 128 atoms.
// B = 2048, NC2 = 8128.
//
// Round-4: register-cj + broadcast-ci (from R3) with restored occupancy:
// 8 warps/block, 4 batches/block, 512 blocks -> 8192 warps (~55/SM).
// Warp w: tile (w&3) on batch (w>>2), then tile 3-(w&3) on batch 2+(w>>2)
// -> exactly 158 rows per warp. Diagonal tile rows split into a predicated
// 31-row prologue + clean main loop.

#define N_ATOMS 128
#define NC2     8128
#define BLOCK_THREADS 256      // 8 warps
#define BPB 4                  // batches per block

__device__ __forceinline__ float nrf_scale() {
    return (float)(627.5095 * 0.529177 / 100.0);
}

__global__ __launch_bounds__(BLOCK_THREADS)
void coords_to_nrf_kernel(const float* __restrict__ coords,
                          const float* __restrict__ atoms_flat,
                          float* __restrict__ out) {
    // Coords for 4 batches, float4-padded: 4*128*16B = 8KB.
    __shared__ float4 sc[BPB][N_ATOMS];

    const int warp = threadIdx.x >> 5;   // 0..7
    const int lane = threadIdx.x & 31;
    const int bg   = blockIdx.x;

    // ---- Stage 4 batches' coords (gmem [b][atom][3] -> float4 smem) ----
    const float* cb = coords + (size_t)bg * BPB * (N_ATOMS * 3);
    float* scf = reinterpret_cast<float*>(sc);
    #pragma unroll
    for (int idx = threadIdx.x; idx < BPB * N_ATOMS * 3; idx += BLOCK_THREADS) {
        const int ba  = idx / 3;
        const int dim = idx - ba * 3;
        scf[ba * 4 + dim] = cb[idx];
    }
    __syncthreads();

    const float scale = nrf_scale();
    const int wt = warp & 3;       // base tile
    const int wb = warp >> 2;      // base batch half

    #pragma unroll
    for (int a = 0; a < 2; a++) {
        const int t   = (a == 0) ? wt : (3 - wt);   // j-tile
        const int bat = (a == 0) ? wb : (2 + wb);   // batch slot in block
        const int j0  = t * 32;
        const int j   = j0 + lane;

        const float4 cj = sc[bat][j];               // registers for the sweep
        float* ob = out + ((size_t)bg * BPB + bat) * NC2;

        int pbase = ((j0 + 1) * j0) >> 1;           // i*(i-1)/2 at i = j0+1

        // --- predicated diagonal rows: i = j0+1 .. j0+31 ---
        #pragma unroll 4
        for (int i = j0 + 1; i < j0 + 32; i++) {
            const float4 ci = sc[bat][i];           // uniform addr -> broadcast
            const float dx = ci.x - cj.x;
            const float dy = ci.y - cj.y;
            const float dz = ci.z - cj.z;
            const float d2 = fmaf(dx, dx, fmaf(dy, dy, dz * dz));
            if (lane < i - j0) {
                const int p = pbase + j;
                ob[p] = __fdividef(__ldg(&atoms_flat[p]) * scale, d2);
            }
            pbase += i;
        }

        // --- full rows: i = j0+32 .. 127 (empty for tile 3) ---
        #pragma unroll 8
        for (int i = j0 + 32; i < N_ATOMS; i++) {
            const float4 ci = sc[bat][i];
            const float dx = ci.x - cj.x;
            const float dy = ci.y - cj.y;
            const float dz = ci.z - cj.z;
            const float d2 = fmaf(dx, dx, fmaf(dy, dy, dz * dz));
            const int p = pbase + j;
            ob[p] = __fdividef(__ldg(&atoms_flat[p]) * scale, d2);
            pbase += i;
        }
    }
}

extern "C" void kernel_launch(void* const* d_in, const int* in_sizes, int n_in,
                              void* d_out, int out_size) {
    const float* coords     = (const float*)d_in[0];  // [2048, 128, 3] f32
    const float* atoms_flat = (const float*)d_in[1];  // [8128] f32
    float* out = (float*)d_out;                       // [2048, 8128] f32

    const int batch = in_sizes[0] / (N_ATOMS * 3);    // 2048
    coords_to_nrf_kernel<<<batch / BPB, BLOCK_THREADS>>>(coords, atoms_flat, out);
}